// round 17
// baseline (speedup 1.0000x reference)
#include <cuda_runtime.h>
#include <cuda_bf16.h>
#include <math.h>
#include <stdint.h>

#define Bz 2
#define Dd 1024
#define Ll 2048
#define Hh 16
#define DKk 64
#define BH 32
typedef uint32_t u32;

__device__ u32 g_xH[(size_t)Bz*Ll*512],  g_xL[(size_t)Bz*Ll*512];
__device__ u32 g_wH[(size_t)3*Hh*DKk*512], g_wL[(size_t)3*Hh*DKk*512];
__device__ u32 g_woH[(size_t)Dd*512],    g_woL[(size_t)Dd*512];
__device__ u32 g_QH[(size_t)BH*Ll*32],   g_QL[(size_t)BH*Ll*32];
__device__ u32 g_KH[(size_t)BH*Ll*32],   g_KL[(size_t)BH*Ll*32];
__device__ u32 g_VtH[(size_t)BH*DKk*1024], g_VtL[(size_t)BH*DKk*1024];
__device__ u32 g_HdH[(size_t)Bz*Ll*512], g_HdL[(size_t)Bz*Ll*512];

extern __shared__ u32 dynsm[];

__device__ __forceinline__ u32 pk(float e, float o) {
    u32 d; asm("cvt.rn.bf16x2.f32 %0, %1, %2;" : "=r"(d) : "f"(o), "f"(e)); return d;
}
__device__ __forceinline__ float bhi(float x) { return __bfloat162float(__float2bfloat16_rn(x)); }
__device__ __forceinline__ void mma16816(float* c, const u32* a, u32 b0, u32 b1) {
    asm("mma.sync.aligned.m16n8k16.row.col.f32.bf16.bf16.f32 "
        "{%0,%1,%2,%3},{%4,%5,%6,%7},{%8,%9},{%0,%1,%2,%3};"
        : "+f"(c[0]), "+f"(c[1]), "+f"(c[2]), "+f"(c[3])
        : "r"(a[0]), "r"(a[1]), "r"(a[2]), "r"(a[3]), "r"(b0), "r"(b1));
}
__device__ __forceinline__ u32 smem_u32(const void* p) {
    u32 a;
    asm("{ .reg .u64 t; cvta.to.shared.u64 t, %1; cvt.u32.u64 %0, t; }" : "=r"(a) : "l"(p));
    return a;
}
__device__ __forceinline__ void ldsm4(u32& r0, u32& r1, u32& r2, u32& r3, u32 addr) {
    asm volatile("ldmatrix.sync.aligned.m8n8.x4.shared.b16 {%0,%1,%2,%3}, [%4];"
                 : "=r"(r0), "=r"(r1), "=r"(r2), "=r"(r3) : "r"(addr));
}
__device__ __forceinline__ void cpa16(u32 dst, const void* src) {
    asm volatile("cp.async.cg.shared.global [%0], [%1], 16;" :: "r"(dst), "l"(src));
}

// ---------------- prep kernels ----------------
__global__ __launch_bounds__(256) void x_split(const float* __restrict__ x) {
    __shared__ float st[64][65];
    int b = blockIdx.z, d0 = blockIdx.y * 64, l0 = blockIdx.x * 64, t = threadIdx.x;
    for (int i = t; i < 64 * 64; i += 256) {
        int dr = i >> 6, lc = i & 63;
        st[dr][lc] = x[((size_t)b * Dd + d0 + dr) * Ll + l0 + lc];
    }
    __syncthreads();
    for (int j = t; j < 64 * 32; j += 256) {
        int l = j >> 5, dp = j & 31;
        float e = st[2 * dp][l], o = st[2 * dp + 1][l];
        float he = bhi(e), ho = bhi(o);
        size_t gi = ((size_t)b * Ll + l0 + l) * 512 + (d0 >> 1) + dp;
        g_xH[gi] = pk(he, ho); g_xL[gi] = pk(e - he, o - ho);
    }
}
__global__ __launch_bounds__(256) void w_split_t(const float* __restrict__ Wq,
                                                 const float* __restrict__ Wk,
                                                 const float* __restrict__ Wv) {
    __shared__ float st[64][65];
    int mat = blockIdx.z, h = blockIdx.y, d0 = blockIdx.x * 64, t = threadIdx.x;
    const float* W = mat == 0 ? Wq : (mat == 1 ? Wk : Wv);
    float s = (mat == 0) ? 0.125f : 1.0f;
    for (int i = t; i < 64 * 64; i += 256) {
        int dr = i >> 6, kc = i & 63;
        st[dr][kc] = W[((size_t)h * Dd + d0 + dr) * DKk + kc] * s;
    }
    __syncthreads();
    for (int j = t; j < 64 * 32; j += 256) {
        int k = j >> 5, dp = j & 31;
        float e = st[2 * dp][k], o = st[2 * dp + 1][k];
        float he = bhi(e), ho = bhi(o);
        size_t gi = ((size_t)(mat * Hh + h) * DKk + k) * 512 + (d0 >> 1) + dp;
        g_wH[gi] = pk(he, ho); g_wL[gi] = pk(e - he, o - ho);
    }
}
__global__ __launch_bounds__(256) void wo_split_t(const float* __restrict__ Wo) {
    __shared__ float st[64][65];
    int e0 = blockIdx.y * 64, d0 = blockIdx.x * 64, t = threadIdx.x;
    for (int i = t; i < 64 * 64; i += 256) {
        int er = i >> 6, dc = i & 63;
        st[er][dc] = Wo[((size_t)(e0 + er)) * Dd + d0 + dc];
    }
    __syncthreads();
    for (int j = t; j < 64 * 32; j += 256) {
        int d = j >> 5, ep = j & 31;
        float e = st[2 * ep][d], o = st[2 * ep + 1][d];
        float he = bhi(e), ho = bhi(o);
        size_t gi = ((size_t)(d0 + d)) * 512 + (e0 >> 1) + ep;
        g_woH[gi] = pk(he, ho); g_woL[gi] = pk(e - he, o - ho);
    }
}

// ------------- 128x64 GEMM body: 8 warps (32x32 sub-tiles), 2-stage, 2 CTAs/SM -------------
#define STG_B 55296
#define S_AH 0
#define S_AL 4608
#define S_BH 9216
#define S_BL 11520

__device__ __forceinline__ void gemm_issue(const u32* aH, const u32* aL,
                                           const u32* bH, const u32* bL,
                                           u32 smb, int kb) {
    int t = threadIdx.x;
    int kp0 = kb * 32;
    u32 sbase = smb + (kb & 1) * STG_B;
    for (int i = t; i < 1024; i += 256) {
        int row = i >> 3, q = (i & 7) * 4;
        u32 off = (row * 36 + q) * 4;
        size_t so = (size_t)row * 512 + kp0 + q;
        cpa16(sbase + S_AH * 4 + off, &aH[so]);
        cpa16(sbase + S_AL * 4 + off, &aL[so]);
    }
    for (int i = t; i < 512; i += 256) {
        int row = i >> 3, q = (i & 7) * 4;
        u32 off = (row * 36 + q) * 4;
        size_t so = (size_t)row * 512 + kp0 + q;
        cpa16(sbase + S_BH * 4 + off, &bH[so]);
        cpa16(sbase + S_BL * 4 + off, &bL[so]);
    }
    asm volatile("cp.async.commit_group;" ::: "memory");
}

__device__ __forceinline__ void gemm_body(const u32* aH, const u32* aL,
                                          const u32* bH, const u32* bL) {
    int t = threadIdx.x, w = t >> 5, lane = t & 31;
    u32 smb = smem_u32(dynsm);
    int m0w = (w >> 1) * 32, n0w = (w & 1) * 32;

    int rowA = (lane & 7) + ((lane >> 3) & 1) * 8;
    int colA = ((lane >> 4) & 1) * 16;
    int rowB = (lane & 7) + ((lane >> 4) & 1) * 8;
    int colB = ((lane >> 3) & 1) * 16;

    float acc[2][4][4];
    #pragma unroll
    for (int mf = 0; mf < 2; mf++)
        #pragma unroll
        for (int nf = 0; nf < 4; nf++)
            #pragma unroll
            for (int c = 0; c < 4; c++) acc[mf][nf][c] = 0.f;

    gemm_issue(aH, aL, bH, bL, smb, 0);
    for (int kb = 0; kb < 16; kb++) {
        __syncthreads();
        if (kb < 15) {
            gemm_issue(aH, aL, bH, bL, smb, kb + 1);
            asm volatile("cp.async.wait_group 1;" ::: "memory");
        } else {
            asm volatile("cp.async.wait_group 0;" ::: "memory");
        }
        __syncthreads();

        u32 sb = smb + (kb & 1) * STG_B;
        #pragma unroll
        for (int kk = 0; kk < 4; kk++) {
            u32 aHf[2][4], aLf[2][4];
            #pragma unroll
            for (int mf = 0; mf < 2; mf++) {
                u32 adr = sb + S_AH * 4 + (u32)(m0w + mf * 16 + rowA) * 144 + kk * 32 + colA;
                ldsm4(aHf[mf][0], aHf[mf][1], aHf[mf][2], aHf[mf][3], adr);
                ldsm4(aLf[mf][0], aLf[mf][1], aLf[mf][2], aLf[mf][3], adr + (S_AL - S_AH) * 4);
            }
            u32 bHf[4][2], bLf[4][2];
            #pragma unroll
            for (int nfp = 0; nfp < 2; nfp++) {
                u32 adr = sb + S_BH * 4 + (u32)(n0w + nfp * 16 + rowB) * 144 + kk * 32 + colB;
                ldsm4(bHf[2*nfp][0], bHf[2*nfp][1], bHf[2*nfp+1][0], bHf[2*nfp+1][1], adr);
                ldsm4(bLf[2*nfp][0], bLf[2*nfp][1], bLf[2*nfp+1][0], bLf[2*nfp+1][1],
                      adr + (S_BL - S_BH) * 4);
            }
            #pragma unroll
            for (int nf = 0; nf < 4; nf++)
                #pragma unroll
                for (int mf = 0; mf < 2; mf++) {
                    mma16816(acc[mf][nf], aHf[mf], bHf[nf][0], bHf[nf][1]);
                    mma16816(acc[mf][nf], aLf[mf], bHf[nf][0], bHf[nf][1]);
                    mma16816(acc[mf][nf], aHf[mf], bLf[nf][0], bLf[nf][1]);
                }
        }
    }

    __syncthreads();
    float* Cs = (float*)dynsm; const int CP = 69;
    int g = lane >> 2, r = lane & 3;
    #pragma unroll
    for (int mf = 0; mf < 2; mf++)
        #pragma unroll
        for (int nf = 0; nf < 4; nf++) {
            int row = m0w + mf * 16 + g, col = n0w + nf * 8 + 2 * r;
            Cs[row * CP + col] = acc[mf][nf][0];
            Cs[row * CP + col + 1] = acc[mf][nf][1];
            Cs[(row + 8) * CP + col] = acc[mf][nf][2];
            Cs[(row + 8) * CP + col + 1] = acc[mf][nf][3];
        }
    __syncthreads();
}

// ---------------- fused QKV GEMM: grid (32, 48), 256 threads ----------------
__global__ __launch_bounds__(256, 2) void qkv_gemm() {
    int brow = blockIdx.x * 128;
    int b = brow >> 11, lloc = brow & 2047;
    int mat = blockIdx.y >> 4, h = blockIdx.y & 15;
    int t = threadIdx.x;

    const size_t wbase = (size_t)(mat * Hh + h) * DKk * 512;
    gemm_body(g_xH + (size_t)brow * 512, g_xL + (size_t)brow * 512,
              g_wH + wbase, g_wL + wbase);

    float* Cs = (float*)dynsm; const int CP = 69;
    if (mat < 2) {
        u32* dH = mat ? g_KH : g_QH;
        u32* dL = mat ? g_KL : g_QL;
        for (int i = t; i < 128 * 32; i += 256) {
            int lr = i >> 5, dkp = i & 31;
            float v0 = Cs[lr * CP + 2 * dkp], v1 = Cs[lr * CP + 2 * dkp + 1];
            float h1 = bhi(v0), h2 = bhi(v1);
            size_t gi = ((size_t)(b * 16 + h) * Ll + lloc + lr) * 32 + dkp;
            dH[gi] = pk(h1, h2); dL[gi] = pk(v0 - h1, v1 - h2);
        }
    } else {
        for (int i = t; i < 64 * 64; i += 256) {
            int dk = i >> 6, lp = i & 63;
            float v0 = Cs[(2 * lp) * CP + dk], v1 = Cs[(2 * lp + 1) * CP + dk];
            float h1 = bhi(v0), h2 = bhi(v1);
            size_t gi = ((size_t)(b * 16 + h) * DKk + dk) * 1024 + (lloc >> 1) + lp;
            g_VtH[gi] = pk(h1, h2); g_VtL[gi] = pk(v0 - h1, v1 - h2);
        }
    }
}

// ---------------- output projection: grid (32, 16), 256 threads ----------------
__global__ __launch_bounds__(256, 2) void oproj_gemm(float* __restrict__ out) {
    int brow = blockIdx.x * 128;
    int b = brow >> 11, lloc = brow & 2047;
    int d0 = blockIdx.y * 64;
    int t = threadIdx.x;

    gemm_body(g_HdH + (size_t)brow * 512, g_HdL + (size_t)brow * 512,
              g_woH + (size_t)d0 * 512, g_woL + (size_t)d0 * 512);

    float* Cs = (float*)dynsm; const int CP = 69;
    for (int i = t; i < 128 * 64; i += 256) {
        int dc = i >> 7, lc = i & 127;
        out[((size_t)b * Dd + d0 + dc) * Ll + lloc + lc] = Cs[lc * CP + dc];
    }
}

// ---------------- flash attention: warp-private softmax, Q in registers ----------------
#define FST0 9216
#define FSSTR 9344
#define FLASH_U32 (9216 + 2 * 9344)

__device__ __forceinline__ void flash_issue(const u32* kH, const u32* kL,
                                            const u32* vH, const u32* vL,
                                            const float* mrow_g, u32 smb, int kb) {
    int t = threadIdx.x;
    u32 sb = smb + (FST0 + (kb & 1) * FSSTR) * 4;
    int kp0 = kb * 32;
    for (int c = t; c < 512; c += 256) {
        int row = c >> 3, q = (c & 7) * 4;
        u32 d = sb + (row * 36 + q) * 4;
        cpa16(d,            &kH[(size_t)(kb * 64 + row) * 32 + q]);
        cpa16(d + 2304 * 4, &kL[(size_t)(kb * 64 + row) * 32 + q]);
        cpa16(d + 4608 * 4, &vH[(size_t)row * 1024 + kp0 + q]);
        cpa16(d + 6912 * 4, &vL[(size_t)row * 1024 + kp0 + q]);
    }
    if (t < 16) cpa16(sb + 9216 * 4 + t * 16, &mrow_g[kb * 64 + t * 4]);
    asm volatile("cp.async.commit_group;" ::: "memory");
}

__global__ __launch_bounds__(256, 2) void flash_mma(const float* __restrict__ mask) {
    int bh = blockIdx.y, b = bh >> 4, h = bh & 15, l0 = blockIdx.x * 128;
    int t = threadIdx.x, w = t >> 5, lane = t & 31, g = lane >> 2, r = lane & 3;
    int m0w = w * 16;
    u32 smb = smem_u32(dynsm);

    int rowA = (lane & 7) + ((lane >> 3) & 1) * 8;
    int colA = ((lane >> 4) & 1) * 16;
    int rowB = (lane & 7) + ((lane >> 4) & 1) * 8;
    int colB = ((lane >> 3) & 1) * 16;

    const u32* kHp = g_KH + (size_t)bh * Ll * 32;
    const u32* kLp = g_KL + (size_t)bh * Ll * 32;
    const u32* vHp = g_VtH + (size_t)bh * DKk * 1024;
    const u32* vLp = g_VtL + (size_t)bh * DKk * 1024;
    const float* mg = mask + (size_t)b * Ll;

    flash_issue(kHp, kLp, vHp, vLp, mg, smb, 0);

    const u32* qH = g_QH + ((size_t)bh * Ll + l0) * 32;
    const u32* qL = g_QL + ((size_t)bh * Ll + l0) * 32;
    for (int i = t; i < 1024; i += 256) {
        int row = i >> 3, q = (i & 7) * 4;
        *(uint4*)&dynsm[row * 36 + q]        = *(const uint4*)&qH[(size_t)row * 32 + q];
        *(uint4*)&dynsm[4608 + row * 36 + q] = *(const uint4*)&qL[(size_t)row * 32 + q];
    }
    __syncthreads();

    // hoist Q fragments into registers (invariant across all key tiles)
    u32 qfH[4][4], qfL[4][4];
    #pragma unroll
    for (int kk = 0; kk < 4; kk++) {
        u32 adrQ = smb + (u32)(m0w + rowA) * 144 + kk * 32 + colA;
        ldsm4(qfH[kk][0], qfH[kk][1], qfH[kk][2], qfH[kk][3], adrQ);
        ldsm4(qfL[kk][0], qfL[kk][1], qfL[kk][2], qfL[kk][3], adrQ + 4608 * 4);
    }

    float O[8][4];
    #pragma unroll
    for (int nf = 0; nf < 8; nf++)
        #pragma unroll
        for (int c = 0; c < 4; c++) O[nf][c] = 0.f;
    float mA = -INFINITY, mB = -INFINITY, lA = 0.f, lB = 0.f;

    for (int kb = 0; kb < 32; kb++) {
        asm volatile("cp.async.wait_group 0;" ::: "memory");
        __syncthreads();
        if (kb < 31) flash_issue(kHp, kLp, vHp, vLp, mg, smb, kb + 1);

        u32 sb = smb + (FST0 + (kb & 1) * FSSTR) * 4;
        float* kms = (float*)(dynsm + FST0 + (kb & 1) * FSSTR + 9216);

        float sa[8][4];
        #pragma unroll
        for (int nf = 0; nf < 8; nf++)
            #pragma unroll
            for (int c = 0; c < 4; c++) sa[nf][c] = 0.f;
        #pragma unroll
        for (int kk = 0; kk < 4; kk++) {
            u32 bH[8][2], bL[8][2];
            #pragma unroll
            for (int nfp = 0; nfp < 4; nfp++) {
                u32 adrK = sb + (u32)(nfp * 16 + rowB) * 144 + kk * 32 + colB;
                ldsm4(bH[2*nfp][0], bH[2*nfp][1], bH[2*nfp+1][0], bH[2*nfp+1][1], adrK);
                ldsm4(bL[2*nfp][0], bL[2*nfp][1], bL[2*nfp+1][0], bL[2*nfp+1][1], adrK + 2304 * 4);
            }
            #pragma unroll
            for (int nf = 0; nf < 8; nf++) {
                mma16816(sa[nf], qfH[kk], bH[nf][0], bH[nf][1]);
                mma16816(sa[nf], qfL[kk], bH[nf][0], bH[nf][1]);
                mma16816(sa[nf], qfH[kk], bL[nf][0], bL[nf][1]);
            }
        }

        float pmA = -INFINITY, pmB = -INFINITY;
        #pragma unroll
        for (int nf = 0; nf < 8; nf++) {
            int kc = nf * 8 + 2 * r;
            bool k0 = kms[kc] > 0.5f, k1 = kms[kc + 1] > 0.5f;
            if (!k0) { sa[nf][0] = -1e30f; sa[nf][2] = -1e30f; }
            if (!k1) { sa[nf][1] = -1e30f; sa[nf][3] = -1e30f; }
            pmA = fmaxf(pmA, fmaxf(sa[nf][0], sa[nf][1]));
            pmB = fmaxf(pmB, fmaxf(sa[nf][2], sa[nf][3]));
        }
        pmA = fmaxf(pmA, __shfl_xor_sync(0xffffffffu, pmA, 1));
        pmA = fmaxf(pmA, __shfl_xor_sync(0xffffffffu, pmA, 2));
        pmB = fmaxf(pmB, __shfl_xor_sync(0xffffffffu, pmB, 1));
        pmB = fmaxf(pmB, __shfl_xor_sync(0xffffffffu, pmB, 2));
        float mnA = fmaxf(mA, pmA), mnB = fmaxf(mB, pmB);
        float alA = __expf(mA - mnA), alB = __expf(mB - mnB);
        float psA = 0.f, psB = 0.f;
        #pragma unroll
        for (int nf = 0; nf < 8; nf++) {
            float e0 = __expf(sa[nf][0] - mnA), e1 = __expf(sa[nf][1] - mnA);
            float e2 = __expf(sa[nf][2] - mnB), e3 = __expf(sa[nf][3] - mnB);
            sa[nf][0] = e0; sa[nf][1] = e1; sa[nf][2] = e2; sa[nf][3] = e3;
            psA += e0 + e1; psB += e2 + e3;
        }
        psA += __shfl_xor_sync(0xffffffffu, psA, 1);
        psA += __shfl_xor_sync(0xffffffffu, psA, 2);
        psB += __shfl_xor_sync(0xffffffffu, psB, 1);
        psB += __shfl_xor_sync(0xffffffffu, psB, 2);
        lA = lA * alA + psA; lB = lB * alB + psB;
        mA = mnA; mB = mnB;
        #pragma unroll
        for (int nf = 0; nf < 8; nf++) {
            O[nf][0] *= alA; O[nf][1] *= alA;
            O[nf][2] *= alB; O[nf][3] *= alB;
        }

        #pragma unroll
        for (int kp = 0; kp < 4; kp++) {
            float e00 = sa[2*kp][0],   e01 = sa[2*kp][1],   e02 = sa[2*kp][2],   e03 = sa[2*kp][3];
            float e10 = sa[2*kp+1][0], e11 = sa[2*kp+1][1], e12 = sa[2*kp+1][2], e13 = sa[2*kp+1][3];
            float h00 = bhi(e00), h01 = bhi(e01), h02 = bhi(e02), h03 = bhi(e03);
            float h10 = bhi(e10), h11 = bhi(e11), h12 = bhi(e12), h13 = bhi(e13);
            u32 pHf[4] = { pk(h00, h01), pk(h02, h03), pk(h10, h11), pk(h12, h13) };
            u32 pLf[4] = { pk(e00 - h00, e01 - h01), pk(e02 - h02, e03 - h03),
                           pk(e10 - h10, e11 - h11), pk(e12 - h12, e13 - h13) };
            u32 bH[8][2], bL[8][2];
            #pragma unroll
            for (int nfp = 0; nfp < 4; nfp++) {
                u32 adrV = sb + 4608 * 4 + (u32)(nfp * 16 + rowB) * 144 + kp * 32 + colB;
                ldsm4(bH[2*nfp][0], bH[2*nfp][1], bH[2*nfp+1][0], bH[2*nfp+1][1], adrV);
                ldsm4(bL[2*nfp][0], bL[2*nfp][1], bL[2*nfp+1][0], bL[2*nfp+1][1], adrV + 2304 * 4);
            }
            #pragma unroll
            for (int nf = 0; nf < 8; nf++) {
                mma16816(O[nf], pHf, bH[nf][0], bH[nf][1]);
                mma16816(O[nf], pLf, bH[nf][0], bH[nf][1]);
                mma16816(O[nf], pHf, bL[nf][0], bL[nf][1]);
            }
        }
    }

    int row = m0w + g;
    float s0 = mg[l0 + row] / lA;
    float s1 = mg[l0 + row + 8] / lB;
    #pragma unroll
    for (int nf = 0; nf < 8; nf++) {
        float c0 = O[nf][0] * s0, c1 = O[nf][1] * s0;
        float c2 = O[nf][2] * s1, c3 = O[nf][3] * s1;
        size_t gi = ((size_t)b * Ll + l0 + row) * 512 + h * 32 + nf * 4 + r;
        float h0 = bhi(c0), h1 = bhi(c1);
        g_HdH[gi] = pk(h0, h1); g_HdL[gi] = pk(c0 - h0, c1 - h1);
        float h2 = bhi(c2), h3 = bhi(c3);
        g_HdH[gi + 8 * 512] = pk(h2, h3);
        g_HdL[gi + 8 * 512] = pk(c2 - h2, c3 - h3);
    }
}

// ---------------------------------------------------------------------------
extern "C" void kernel_launch(void* const* d_in, const int* in_sizes, int n_in,
                              void* d_out, int out_size) {
    const float* x    = (const float*)d_in[0];
    const float* mask = (const float*)d_in[1];
    const float* Wq   = (const float*)d_in[2];
    const float* Wk   = (const float*)d_in[3];
    const float* Wv   = (const float*)d_in[4];
    const float* Wo   = (const float*)d_in[5];
    float* out = (float*)d_out;

    const int GEMM_SMEM  = 2 * STG_B;        // 110592 B -> 2 CTAs/SM
    const int FLASH_SMEM = FLASH_U32 * 4;    // 111616 B -> 2 CTAs/SM
    cudaFuncSetAttribute(qkv_gemm,  cudaFuncAttributeMaxDynamicSharedMemorySize, GEMM_SMEM);
    cudaFuncSetAttribute(oproj_gemm, cudaFuncAttributeMaxDynamicSharedMemorySize, GEMM_SMEM);
    cudaFuncSetAttribute(flash_mma, cudaFuncAttributeMaxDynamicSharedMemorySize, FLASH_SMEM);

    x_split<<<dim3(Ll / 64, Dd / 64, Bz), 256>>>(x);
    w_split_t<<<dim3(Dd / 64, Hh, 3), 256>>>(Wq, Wk, Wv);
    wo_split_t<<<dim3(Dd / 64, Dd / 64), 256>>>(Wo);
    qkv_gemm<<<dim3(32, 48), 256, GEMM_SMEM>>>();
    flash_mma<<<dim3(Ll / 128, BH), 256, FLASH_SMEM>>>(mask);
    oproj_gemm<<<dim3(32, 16), 256, GEMM_SMEM>>>(out);
}